// round 15
// baseline (speedup 1.0000x reference)
#include <cuda_runtime.h>
#include <cuda_fp16.h>

#define N_NODES   50000
#define N_EDGES   800000
#define F_IN      16
#define F_EDGE    8
#define H         8
#define NUM_GRAPHS 512

// ---------------- scratch (no allocations allowed) ----------------
// y tables in fp16: one node row = 64 halves = 128B = 1 cache line
__device__ __half g_y1 [N_NODES * F_EDGE * H];
__device__ __half g_xb1[N_NODES * H];
__device__ float  g_agg1[N_NODES * H];
__device__ __half g_y2 [N_NODES * F_EDGE * H];
__device__ __half g_xb2[N_NODES * H];
__device__ float  g_agg2[N_NODES * H];
__device__ int    g_xbflag[2];    // [layer]: 1 if any xb value is nonzero

__device__ __forceinline__ void red_add_v4(float* p, float a, float b, float c, float d) {
    asm volatile("red.global.add.v4.f32 [%0], {%1,%2,%3,%4};"
                 :: "l"(p), "f"(a), "f"(b), "f"(c), "f"(d) : "memory");
}

__device__ __forceinline__ void store_row_half(__half* base, int n, int o, const float* yv) {
    __half2 p0 = __floats2half2_rn(yv[0], yv[1]);
    __half2 p1 = __floats2half2_rn(yv[2], yv[3]);
    __half2 p2 = __floats2half2_rn(yv[4], yv[5]);
    __half2 p3 = __floats2half2_rn(yv[6], yv[7]);
    uint4 u;
    u.x = *(unsigned*)&p0; u.y = *(unsigned*)&p1;
    u.z = *(unsigned*)&p2; u.w = *(unsigned*)&p3;
    *((uint4*)(base + (size_t)n * (F_EDGE * H)) + o) = u;
}

// ---------------- kernel 0: zero the xb flags (must precede node kernels) --------
__global__ void flag_init() {
    if (threadIdx.x < 2) g_xbflag[threadIdx.x] = 0;
}

// ---------------- kernel A: per-node precompute for layer 1 ----------------
__global__ void node_pre1(const float* __restrict__ x,
                          const float* __restrict__ We1,
                          const float* __restrict__ be1,
                          const float* __restrict__ root1,
                          const float* __restrict__ b1,
                          int N)
{
    __shared__ float sW[F_EDGE * F_IN * H];   // 1024
    __shared__ float sbe[F_IN * H];
    __shared__ float sroot[F_IN * H];
    __shared__ float sb[H];

    for (int t = threadIdx.x; t < F_EDGE * F_IN * H; t += blockDim.x) sW[t] = We1[t];
    for (int t = threadIdx.x; t < F_IN * H; t += blockDim.x) { sbe[t] = be1[t]; sroot[t] = root1[t]; }
    if (threadIdx.x < H) sb[threadIdx.x] = b1[threadIdx.x];
    __syncthreads();

    int gt = blockIdx.x * blockDim.x + threadIdx.x;
    int n = gt >> 3;
    int o = gt & 7;
    if (n >= N) return;

    float xv[F_IN];
    const float4* xp = (const float4*)(x + (size_t)n * F_IN);
    float4 v0 = xp[0], v1 = xp[1], v2 = xp[2], v3 = xp[3];
    xv[0]=v0.x; xv[1]=v0.y; xv[2]=v0.z; xv[3]=v0.w;
    xv[4]=v1.x; xv[5]=v1.y; xv[6]=v1.z; xv[7]=v1.w;
    xv[8]=v2.x; xv[9]=v2.y; xv[10]=v2.z; xv[11]=v2.w;
    xv[12]=v3.x; xv[13]=v3.y; xv[14]=v3.z; xv[15]=v3.w;

    float yv[F_EDGE];
    #pragma unroll
    for (int j = 0; j < F_EDGE; j++) {
        float acc = 0.f;
        #pragma unroll
        for (int i = 0; i < F_IN; i++) acc += xv[i] * sW[j * (F_IN * H) + i * H + o];
        yv[j] = acc;
    }
    store_row_half(g_y1, n, o, yv);

    float xb = 0.f, r = sb[o];
    #pragma unroll
    for (int i = 0; i < F_IN; i++) {
        xb += xv[i] * sbe[i * H + o];
        r  += xv[i] * sroot[i * H + o];
    }
    __half xh = __float2half_rn(xb);
    g_xb1[n * H + o] = xh;
    g_agg1[n * H + o] = r;

    // dynamic bias-zero detection: one atomicOr per warp that sees any nonzero xb
    unsigned nz = (__half_as_ushort(xh) & 0x7fffu) != 0;
    if (__any_sync(0xffffffffu, nz) && (threadIdx.x & 31) == 0)
        atomicOr(&g_xbflag[0], 1);
}

// ---------------- edge scatter: 8 thr/edge, flag-gated xb, v4 RED ----------------
__global__ void edge_scatter(const float* __restrict__ ea_g,
                             const int*   __restrict__ ei,
                             const __half* __restrict__ y,
                             const __half* __restrict__ xb,
                             const int*   __restrict__ flag,
                             float*       __restrict__ agg,
                             int E)
{
    int t = blockIdx.x * blockDim.x + threadIdx.x;
    int e = t >> 3;
    int o = t & 7;
    bool valid = (e < E);

    float m = 0.f;
    int dst = 0;
    if (valid) {
        int src = __ldg(ei + e);
        dst     = __ldg(ei + E + e);

        // edge-attr: per edge 32B broadcast across its 8 lanes; warp covers one 128B line/instr
        const float4* eap = (const float4*)(ea_g + (size_t)e * F_EDGE);
        float4 ea0 = __ldg(eap);
        float4 ea1 = __ldg(eap + 1);

        // one 16B load per lane; 8 lanes cover the node's whole 128B fp16 row
        uint4 yv = __ldg((const uint4*)(y + (size_t)src * (F_EDGE * H)) + o);
        float2 f0 = __half22float2(*(__half2*)&yv.x);
        float2 f1 = __half22float2(*(__half2*)&yv.y);
        float2 f2 = __half22float2(*(__half2*)&yv.z);
        float2 f3 = __half22float2(*(__half2*)&yv.w);

        m = ea0.x*f0.x + ea0.y*f0.y + ea0.z*f1.x + ea0.w*f1.y
          + ea1.x*f2.x + ea1.y*f2.y + ea1.z*f3.x + ea1.w*f3.y;

        // bias-path gather only if the edge-MLP bias is actually nonzero
        if (__ldg(flag)) m += __half2float(__ldg(xb + (size_t)src * H + o));
    }

    // assemble 4 contiguous channels into one lane, single vector RED
    unsigned mask = 0xffffffffu;
    int lane = t & 31;
    int base = lane & ~3;
    float v0 = __shfl_sync(mask, m, base);
    float v1 = __shfl_sync(mask, m, base + 1);
    float v2 = __shfl_sync(mask, m, base + 2);
    float v3 = __shfl_sync(mask, m, base + 3);

    if (valid && (lane & 3) == 0) {
        red_add_v4(agg + (size_t)dst * H + (lane & 4), v0, v1, v2, v3);
    }
}

// ---------------- kernel C: relu(layer1) + precompute layer 2 (+ out init) ----------------
__global__ void node_mid(const float* __restrict__ We2,
                         const float* __restrict__ be2,
                         const float* __restrict__ root2,
                         const float* __restrict__ b2,
                         const float* __restrict__ blast,
                         float* __restrict__ out,
                         int N, int G)
{
    __shared__ float sW[F_EDGE * H * H];   // 512
    __shared__ float sbe[H * H];
    __shared__ float sroot[H * H];
    __shared__ float sb[H];

    for (int t = threadIdx.x; t < F_EDGE * H * H; t += blockDim.x) sW[t] = We2[t];
    for (int t = threadIdx.x; t < H * H; t += blockDim.x) { sbe[t] = be2[t]; sroot[t] = root2[t]; }
    if (threadIdx.x < H) sb[threadIdx.x] = b2[threadIdx.x];
    __syncthreads();

    int gt = blockIdx.x * blockDim.x + threadIdx.x;
    if (gt < G) out[gt] = blast[0];        // fold output-bias init into this pass

    int n = gt >> 3;
    int o = gt & 7;
    if (n >= N) return;

    float h[H];
    const float4* ap = (const float4*)(g_agg1 + (size_t)n * H);
    float4 a0 = ap[0], a1 = ap[1];
    h[0]=fmaxf(a0.x,0.f); h[1]=fmaxf(a0.y,0.f); h[2]=fmaxf(a0.z,0.f); h[3]=fmaxf(a0.w,0.f);
    h[4]=fmaxf(a1.x,0.f); h[5]=fmaxf(a1.y,0.f); h[6]=fmaxf(a1.z,0.f); h[7]=fmaxf(a1.w,0.f);

    float yv[F_EDGE];
    #pragma unroll
    for (int j = 0; j < F_EDGE; j++) {
        float acc = 0.f;
        #pragma unroll
        for (int i = 0; i < H; i++) acc += h[i] * sW[j * (H * H) + i * H + o];
        yv[j] = acc;
    }
    store_row_half(g_y2, n, o, yv);

    float xb = 0.f, r = sb[o];
    #pragma unroll
    for (int i = 0; i < H; i++) {
        xb += h[i] * sbe[i * H + o];
        r  += h[i] * sroot[i * H + o];
    }
    __half xh = __float2half_rn(xb);
    g_xb2[n * H + o] = xh;
    g_agg2[n * H + o] = r;

    unsigned nz = (__half_as_ushort(xh) & 0x7fffu) != 0;
    if (__any_sync(0xffffffffu, nz) && (threadIdx.x & 31) == 0)
        atomicOr(&g_xbflag[1], 1);
}

// ---------------- kernel E: relu(layer2) + pool + readout ----------------
__global__ void pool_out(const int* __restrict__ batch,
                         const float* __restrict__ Wlast,
                         float* __restrict__ out,
                         int N)
{
    int n = blockIdx.x * blockDim.x + threadIdx.x;
    int lane = threadIdx.x & 31;
    float s = 0.f;
    int b = -1;
    if (n < N) {
        const float4* ap = (const float4*)(g_agg2 + (size_t)n * H);
        float4 a0 = ap[0], a1 = ap[1];
        s += fmaxf(a0.x,0.f) * __ldg(Wlast + 0);
        s += fmaxf(a0.y,0.f) * __ldg(Wlast + 1);
        s += fmaxf(a0.z,0.f) * __ldg(Wlast + 2);
        s += fmaxf(a0.w,0.f) * __ldg(Wlast + 3);
        s += fmaxf(a1.x,0.f) * __ldg(Wlast + 4);
        s += fmaxf(a1.y,0.f) * __ldg(Wlast + 5);
        s += fmaxf(a1.z,0.f) * __ldg(Wlast + 6);
        s += fmaxf(a1.w,0.f) * __ldg(Wlast + 7);
        b = __ldg(batch + n);
    }
    #pragma unroll
    for (int off = 1; off < 32; off <<= 1) {
        float s2 = __shfl_down_sync(0xffffffffu, s, off);
        int   b2 = __shfl_down_sync(0xffffffffu, b, off);
        if (lane + off < 32 && b2 == b) s += s2;
    }
    int bprev = __shfl_up_sync(0xffffffffu, b, 1);
    bool leader = (lane == 0) || (bprev != b);
    if (n < N && leader) atomicAdd(&out[b], s);
}

// ---------------- launch ----------------
extern "C" void kernel_launch(void* const* d_in, const int* in_sizes, int n_in,
                              void* d_out, int out_size)
{
    const float* x         = (const float*)d_in[0];
    const int*   edge_index= (const int*)  d_in[1];
    const float* edge_attr = (const float*)d_in[2];
    const int*   batch     = (const int*)  d_in[3];
    const float* We1       = (const float*)d_in[4];
    const float* be1       = (const float*)d_in[5];
    const float* root1     = (const float*)d_in[6];
    const float* b1        = (const float*)d_in[7];
    const float* We2       = (const float*)d_in[8];
    const float* be2       = (const float*)d_in[9];
    const float* root2     = (const float*)d_in[10];
    const float* b2        = (const float*)d_in[11];
    const float* Wlast     = (const float*)d_in[12];
    const float* blast     = (const float*)d_in[13];
    float* out = (float*)d_out;

    int N = in_sizes[0] / F_IN;
    int E = in_sizes[1] / 2;
    int G = out_size;

    __half *y1, *xb1, *y2, *xb2;
    float *agg1, *agg2;
    int *flags;
    cudaGetSymbolAddress((void**)&y1,  g_y1);
    cudaGetSymbolAddress((void**)&xb1, g_xb1);
    cudaGetSymbolAddress((void**)&agg1,g_agg1);
    cudaGetSymbolAddress((void**)&y2,  g_y2);
    cudaGetSymbolAddress((void**)&xb2, g_xb2);
    cudaGetSymbolAddress((void**)&agg2,g_agg2);
    cudaGetSymbolAddress((void**)&flags, g_xbflag);

    dim3 blk(256);
    int node_blocks = (N * H + 255) / 256;
    int edge_blocks = (E * H + 255) / 256;

    flag_init<<<1, 32>>>();
    node_pre1<<<node_blocks, blk>>>(x, We1, be1, root1, b1, N);
    edge_scatter<<<edge_blocks, blk>>>(edge_attr, edge_index, y1, xb1, flags + 0, agg1, E);
    node_mid<<<node_blocks, blk>>>(We2, be2, root2, b2, blast, out, N, G);
    edge_scatter<<<edge_blocks, blk>>>(edge_attr, edge_index, y2, xb2, flags + 1, agg2, E);
    pool_out<<<(N + 255) / 256, blk>>>(batch, Wlast, out, N);
}

// round 17
// speedup vs baseline: 1.1906x; 1.1906x over previous
#include <cuda_runtime.h>
#include <cuda_fp16.h>

#define N_NODES   50000
#define N_EDGES   800000
#define F_IN      16
#define F_EDGE    8
#define H         8
#define NUM_GRAPHS 512

// ---------------- scratch (no allocations allowed) ----------------
// y tables in fp16: one node row = 64 halves = 128B = 1 cache line, o-major: y[n][o][j]
__device__ __half g_y1 [N_NODES * F_EDGE * H];
__device__ __half g_xb1[N_NODES * H];
__device__ float  g_agg1[N_NODES * H];
__device__ __half g_y2 [N_NODES * F_EDGE * H];
__device__ __half g_xb2[N_NODES * H];
__device__ float  g_agg2[N_NODES * H];
__device__ int    g_xbflag[2];    // statically zero; reset at end of pool_out each run

__device__ __forceinline__ void red_add_v4(float* p, float a, float b, float c, float d) {
    asm volatile("red.global.add.v4.f32 [%0], {%1,%2,%3,%4};"
                 :: "l"(p), "f"(a), "f"(b), "f"(c), "f"(d) : "memory");
}

__device__ __forceinline__ void store_row_half(__half* base, int n, int o, const float* yv) {
    __half2 p0 = __floats2half2_rn(yv[0], yv[1]);
    __half2 p1 = __floats2half2_rn(yv[2], yv[3]);
    __half2 p2 = __floats2half2_rn(yv[4], yv[5]);
    __half2 p3 = __floats2half2_rn(yv[6], yv[7]);
    uint4 u;
    u.x = *(unsigned*)&p0; u.y = *(unsigned*)&p1;
    u.z = *(unsigned*)&p2; u.w = *(unsigned*)&p3;
    *((uint4*)(base + (size_t)n * (F_EDGE * H)) + o) = u;
}

// ---------------- kernel A: per-node precompute for layer 1 ----------------
// transposed weight smem: sWT[o][j][i], stride per o = 132 floats (16B-aligned, bank-staggered)
#define W1_STRIDE (F_EDGE * F_IN + 4)   // 132
__global__ void node_pre1(const float* __restrict__ x,
                          const float* __restrict__ We1,
                          const float* __restrict__ be1,
                          const float* __restrict__ root1,
                          const float* __restrict__ b1,
                          int N)
{
    __shared__ float sWT[H * W1_STRIDE];      // 1056
    __shared__ float sbe[F_IN * H];
    __shared__ float sroot[F_IN * H];
    __shared__ float sb[H];

    for (int t = threadIdx.x; t < F_EDGE * F_IN * H; t += blockDim.x) {
        int o = t >> 7, j = (t >> 4) & 7, i = t & 15;
        sWT[o * W1_STRIDE + j * F_IN + i] = We1[j * (F_IN * H) + i * H + o];
    }
    for (int t = threadIdx.x; t < F_IN * H; t += blockDim.x) { sbe[t] = be1[t]; sroot[t] = root1[t]; }
    if (threadIdx.x < H) sb[threadIdx.x] = b1[threadIdx.x];
    __syncthreads();

    int gt = blockIdx.x * blockDim.x + threadIdx.x;
    int n = gt >> 3;
    int o = gt & 7;
    if (n >= N) return;

    float xv[F_IN];
    const float4* xp = (const float4*)(x + (size_t)n * F_IN);
    float4 v0 = xp[0], v1 = xp[1], v2 = xp[2], v3 = xp[3];
    xv[0]=v0.x; xv[1]=v0.y; xv[2]=v0.z; xv[3]=v0.w;
    xv[4]=v1.x; xv[5]=v1.y; xv[6]=v1.z; xv[7]=v1.w;
    xv[8]=v2.x; xv[9]=v2.y; xv[10]=v2.z; xv[11]=v2.w;
    xv[12]=v3.x; xv[13]=v3.y; xv[14]=v3.z; xv[15]=v3.w;

    float yv[F_EDGE];
    const float4* wbase = (const float4*)(sWT + o * W1_STRIDE);
    #pragma unroll
    for (int j = 0; j < F_EDGE; j++) {
        float4 w0 = wbase[j*4+0], w1 = wbase[j*4+1], w2 = wbase[j*4+2], w3 = wbase[j*4+3];
        yv[j] = xv[0]*w0.x + xv[1]*w0.y + xv[2]*w0.z + xv[3]*w0.w
              + xv[4]*w1.x + xv[5]*w1.y + xv[6]*w1.z + xv[7]*w1.w
              + xv[8]*w2.x + xv[9]*w2.y + xv[10]*w2.z + xv[11]*w2.w
              + xv[12]*w3.x + xv[13]*w3.y + xv[14]*w3.z + xv[15]*w3.w;
    }
    store_row_half(g_y1, n, o, yv);

    float xb = 0.f, r = sb[o];
    #pragma unroll
    for (int i = 0; i < F_IN; i++) {
        xb += xv[i] * sbe[i * H + o];
        r  += xv[i] * sroot[i * H + o];
    }
    __half xh = __float2half_rn(xb);
    g_xb1[n * H + o] = xh;
    g_agg1[n * H + o] = r;

    unsigned nz = (__half_as_ushort(xh) & 0x7fffu) != 0;
    if (__any_sync(0xffffffffu, nz) && (threadIdx.x & 31) == 0)
        atomicOr(&g_xbflag[0], 1);
}

// ---------------- edge scatter: 4 lanes/edge, 2 channels/lane ----------------
// warp = 8 edges. Lane kg = lane&3 owns channels 2kg, 2kg+1 (32B slice of y row).
__global__ void edge_scatter(const float* __restrict__ ea_g,
                             const int*   __restrict__ ei,
                             const __half* __restrict__ y,
                             const __half* __restrict__ xb,
                             const int*   __restrict__ flag,
                             float*       __restrict__ agg,
                             int E)
{
    int t = blockIdx.x * blockDim.x + threadIdx.x;
    int e  = t >> 2;
    int kg = t & 3;
    bool valid = (e < E);

    float m0 = 0.f, m1 = 0.f;
    int dst = 0;
    if (valid) {
        int src = __ldg(ei + e);
        dst     = __ldg(ei + E + e);

        const float4* eap = (const float4*)(ea_g + (size_t)e * F_EDGE);
        float4 ea0 = __ldg(eap);
        float4 ea1 = __ldg(eap + 1);

        const uint4* yp = (const uint4*)(y + (size_t)src * (F_EDGE * H)) + kg * 2;
        uint4 ya = __ldg(yp);
        uint4 yb = __ldg(yp + 1);

        float2 f0 = __half22float2(*(__half2*)&ya.x);
        float2 f1 = __half22float2(*(__half2*)&ya.y);
        float2 f2 = __half22float2(*(__half2*)&ya.z);
        float2 f3 = __half22float2(*(__half2*)&ya.w);
        m0 = ea0.x*f0.x + ea0.y*f0.y + ea0.z*f1.x + ea0.w*f1.y
           + ea1.x*f2.x + ea1.y*f2.y + ea1.z*f3.x + ea1.w*f3.y;

        f0 = __half22float2(*(__half2*)&yb.x);
        f1 = __half22float2(*(__half2*)&yb.y);
        f2 = __half22float2(*(__half2*)&yb.z);
        f3 = __half22float2(*(__half2*)&yb.w);
        m1 = ea0.x*f0.x + ea0.y*f0.y + ea0.z*f1.x + ea0.w*f1.y
           + ea1.x*f2.x + ea1.y*f2.y + ea1.z*f3.x + ea1.w*f3.y;

        if (__ldg(flag)) {   // edge-MLP bias path (uniform branch; be==0 -> skipped)
            __half2 hx = __ldg((const __half2*)(xb + (size_t)src * H) + kg);
            float2 fx = __half22float2(hx);
            m0 += fx.x; m1 += fx.y;
        }
    }

    unsigned mask = 0xffffffffu;
    float v2 = __shfl_down_sync(mask, m0, 1);
    float v3 = __shfl_down_sync(mask, m1, 1);

    int lane = t & 31;
    if (valid && (lane & 1) == 0) {
        // channels 2kg..2kg+3, base = 2*kg with kg even = (lane&2)*2
        red_add_v4(agg + (size_t)dst * H + (lane & 2) * 2, m0, m1, v2, v3);
    }
}

// ---------------- kernel C: relu(layer1) + precompute layer 2 (+ out init) ----------------
#define W2_STRIDE (F_EDGE * H + 4)   // 68
__global__ void node_mid(const float* __restrict__ We2,
                         const float* __restrict__ be2,
                         const float* __restrict__ root2,
                         const float* __restrict__ b2,
                         const float* __restrict__ blast,
                         float* __restrict__ out,
                         int N, int G)
{
    __shared__ float sWT[H * W2_STRIDE];      // 544
    __shared__ float sbe[H * H];
    __shared__ float sroot[H * H];
    __shared__ float sb[H];

    for (int t = threadIdx.x; t < F_EDGE * H * H; t += blockDim.x) {
        int o = t >> 6, j = (t >> 3) & 7, i = t & 7;
        sWT[o * W2_STRIDE + j * H + i] = We2[j * (H * H) + i * H + o];
    }
    for (int t = threadIdx.x; t < H * H; t += blockDim.x) { sbe[t] = be2[t]; sroot[t] = root2[t]; }
    if (threadIdx.x < H) sb[threadIdx.x] = b2[threadIdx.x];
    __syncthreads();

    int gt = blockIdx.x * blockDim.x + threadIdx.x;
    if (gt < G) out[gt] = blast[0];        // fold output-bias init into this pass

    int n = gt >> 3;
    int o = gt & 7;
    if (n >= N) return;

    float h[H];
    const float4* ap = (const float4*)(g_agg1 + (size_t)n * H);
    float4 a0 = ap[0], a1 = ap[1];
    h[0]=fmaxf(a0.x,0.f); h[1]=fmaxf(a0.y,0.f); h[2]=fmaxf(a0.z,0.f); h[3]=fmaxf(a0.w,0.f);
    h[4]=fmaxf(a1.x,0.f); h[5]=fmaxf(a1.y,0.f); h[6]=fmaxf(a1.z,0.f); h[7]=fmaxf(a1.w,0.f);

    float yv[F_EDGE];
    const float4* wbase = (const float4*)(sWT + o * W2_STRIDE);
    #pragma unroll
    for (int j = 0; j < F_EDGE; j++) {
        float4 w0 = wbase[j*2+0], w1 = wbase[j*2+1];
        yv[j] = h[0]*w0.x + h[1]*w0.y + h[2]*w0.z + h[3]*w0.w
              + h[4]*w1.x + h[5]*w1.y + h[6]*w1.z + h[7]*w1.w;
    }
    store_row_half(g_y2, n, o, yv);

    float xb = 0.f, r = sb[o];
    #pragma unroll
    for (int i = 0; i < H; i++) {
        xb += h[i] * sbe[i * H + o];
        r  += h[i] * sroot[i * H + o];
    }
    __half xh = __float2half_rn(xb);
    g_xb2[n * H + o] = xh;
    g_agg2[n * H + o] = r;

    unsigned nz = (__half_as_ushort(xh) & 0x7fffu) != 0;
    if (__any_sync(0xffffffffu, nz) && (threadIdx.x & 31) == 0)
        atomicOr(&g_xbflag[1], 1);
}

// ---------------- kernel E: relu(layer2) + pool + readout (+ flag reset) ----------------
__global__ void pool_out(const int* __restrict__ batch,
                         const float* __restrict__ Wlast,
                         float* __restrict__ out,
                         int N)
{
    int n = blockIdx.x * blockDim.x + threadIdx.x;
    int lane = threadIdx.x & 31;
    if (n == 0) { g_xbflag[0] = 0; g_xbflag[1] = 0; }   // reset for next replay
    float s = 0.f;
    int b = -1;
    if (n < N) {
        const float4* ap = (const float4*)(g_agg2 + (size_t)n * H);
        float4 a0 = ap[0], a1 = ap[1];
        s += fmaxf(a0.x,0.f) * __ldg(Wlast + 0);
        s += fmaxf(a0.y,0.f) * __ldg(Wlast + 1);
        s += fmaxf(a0.z,0.f) * __ldg(Wlast + 2);
        s += fmaxf(a0.w,0.f) * __ldg(Wlast + 3);
        s += fmaxf(a1.x,0.f) * __ldg(Wlast + 4);
        s += fmaxf(a1.y,0.f) * __ldg(Wlast + 5);
        s += fmaxf(a1.z,0.f) * __ldg(Wlast + 6);
        s += fmaxf(a1.w,0.f) * __ldg(Wlast + 7);
        b = __ldg(batch + n);
    }
    #pragma unroll
    for (int off = 1; off < 32; off <<= 1) {
        float s2 = __shfl_down_sync(0xffffffffu, s, off);
        int   b2 = __shfl_down_sync(0xffffffffu, b, off);
        if (lane + off < 32 && b2 == b) s += s2;
    }
    int bprev = __shfl_up_sync(0xffffffffu, b, 1);
    bool leader = (lane == 0) || (bprev != b);
    if (n < N && leader) atomicAdd(&out[b], s);
}

// ---------------- launch ----------------
extern "C" void kernel_launch(void* const* d_in, const int* in_sizes, int n_in,
                              void* d_out, int out_size)
{
    const float* x         = (const float*)d_in[0];
    const int*   edge_index= (const int*)  d_in[1];
    const float* edge_attr = (const float*)d_in[2];
    const int*   batch     = (const int*)  d_in[3];
    const float* We1       = (const float*)d_in[4];
    const float* be1       = (const float*)d_in[5];
    const float* root1     = (const float*)d_in[6];
    const float* b1        = (const float*)d_in[7];
    const float* We2       = (const float*)d_in[8];
    const float* be2       = (const float*)d_in[9];
    const float* root2     = (const float*)d_in[10];
    const float* b2        = (const float*)d_in[11];
    const float* Wlast     = (const float*)d_in[12];
    const float* blast     = (const float*)d_in[13];
    float* out = (float*)d_out;

    int N = in_sizes[0] / F_IN;
    int E = in_sizes[1] / 2;
    int G = out_size;

    __half *y1, *xb1, *y2, *xb2;
    float *agg1, *agg2;
    int *flags;
    cudaGetSymbolAddress((void**)&y1,  g_y1);
    cudaGetSymbolAddress((void**)&xb1, g_xb1);
    cudaGetSymbolAddress((void**)&agg1,g_agg1);
    cudaGetSymbolAddress((void**)&y2,  g_y2);
    cudaGetSymbolAddress((void**)&xb2, g_xb2);
    cudaGetSymbolAddress((void**)&agg2,g_agg2);
    cudaGetSymbolAddress((void**)&flags, g_xbflag);

    dim3 blk(256);
    int node_blocks = (N * H + 255) / 256;
    int edge_blocks = (E * 4 + 255) / 256;

    node_pre1<<<node_blocks, blk>>>(x, We1, be1, root1, b1, N);
    edge_scatter<<<edge_blocks, blk>>>(edge_attr, edge_index, y1, xb1, flags + 0, agg1, E);
    node_mid<<<node_blocks, blk>>>(We2, be2, root2, b2, blast, out, N, G);
    edge_scatter<<<edge_blocks, blk>>>(edge_attr, edge_index, y2, xb2, flags + 1, agg2, E);
    pool_out<<<(N + 255) / 256, blk>>>(batch, Wlast, out, N);
}